// round 13
// baseline (speedup 1.0000x reference)
#include <cuda_runtime.h>
#include <cuda_fp16.h>
#include <cstdint>

namespace {
constexpr int B_      = 2;
constexpr int N_      = 2048;
constexpr int DIM_    = 1024;
constexpr int HEADS_  = 8;
constexpr int DHEAD_  = 64;
constexpr int INNER_  = 512;
constexpr int QKVN_   = 1536;
constexpr float EPS_  = 1e-5f;
constexpr int NCHUNK_ = 16;
constexpr int CH_     = N_ / NCHUNK_;
constexpr float QSCALE_ = 0.125f * 1.4426950408889634f;  // 0.125 * log2(e)
constexpr int PREP_BLOCKS_ = 592;   // 4 blocks/SM on 148 SMs: all co-resident
}

// Scratch. ALL inter-kernel tensors single fp16.
__device__ __half g_xn16[B_ * N_ * DIM_];
__device__ __half g_q16 [B_ * N_ * INNER_];
__device__ __half g_kv16[B_ * N_ * 2 * INNER_];
__device__ __half g_att16[B_ * N_ * INNER_];
__device__ __half g_wqkv16[DIM_ * QKVN_];
__device__ __half g_wo16  [INNER_ * DIM_];
__device__ float g_ps [B_ * NCHUNK_ * DIM_];
__device__ float g_pss[B_ * NCHUNK_ * DIM_];
__device__ float g_scale[B_ * DIM_];
__device__ float g_bias [B_ * DIM_];
__device__ int   g_sync[2];   // [0]=ticket, [1]=flag; reset by memsetAsync per call

// ---------------------------------------------------------------------------
// Helpers
// ---------------------------------------------------------------------------
__device__ __forceinline__ uint32_t pack2h(float x, float y) {
    __half2 p = __halves2half2(__float2half_rn(x), __float2half_rn(y));
    return *reinterpret_cast<uint32_t*>(&p);
}
__device__ __forceinline__ uint32_t ex2_2h(float s0, float s1) {
    uint32_t r;
    asm("{\n.reg .b32 t;\n"
        "cvt.rn.f16x2.f32 t, %2, %1;\n"
        "ex2.approx.f16x2 %0, t;\n}"
        : "=r"(r) : "f"(s0), "f"(s1));
    return r;
}

__device__ __forceinline__ void mma16816(float* c, const uint32_t* a, const uint32_t* b) {
    asm volatile(
        "mma.sync.aligned.m16n8k16.row.col.f32.f16.f16.f32 "
        "{%0,%1,%2,%3},{%4,%5,%6,%7},{%8,%9},{%0,%1,%2,%3};\n"
        : "+f"(c[0]), "+f"(c[1]), "+f"(c[2]), "+f"(c[3])
        : "r"(a[0]), "r"(a[1]), "r"(a[2]), "r"(a[3]), "r"(b[0]), "r"(b[1]));
}

__device__ __forceinline__ uint32_t smem_u32(const void* p) {
    return (uint32_t)__cvta_generic_to_shared(p);
}
__device__ __forceinline__ void ldm_x4(uint32_t* r, uint32_t a) {
    asm volatile("ldmatrix.sync.aligned.m8n8.x4.shared.b16 {%0,%1,%2,%3},[%4];"
                 : "=r"(r[0]), "=r"(r[1]), "=r"(r[2]), "=r"(r[3]) : "r"(a));
}
__device__ __forceinline__ void ldm_x4_t(uint32_t* r, uint32_t a) {
    asm volatile("ldmatrix.sync.aligned.m8n8.x4.trans.shared.b16 {%0,%1,%2,%3},[%4];"
                 : "=r"(r[0]), "=r"(r[1]), "=r"(r[2]), "=r"(r[3]) : "r"(a));
}
__device__ __forceinline__ void cp16(uint32_t dst, const void* src) {
    asm volatile("cp.async.cg.shared.global [%0],[%1],16;\n" :: "r"(dst), "l"(src));
}
__device__ __forceinline__ void cp_commit() {
    asm volatile("cp.async.commit_group;\n" ::: "memory");
}
__device__ __forceinline__ void cp_wait1() {
    asm volatile("cp.async.wait_group 1;\n" ::: "memory");
}

// Swizzles (16B chunk granularity)
__device__ __forceinline__ uint32_t swzA(int r, int c) {   // 64B rows
    return (uint32_t)(r * 64 + ((c ^ ((r >> 1) & 3)) << 4));
}
__device__ __forceinline__ uint32_t swzB(int r, int c) {   // 256B rows
    return (uint32_t)(r * 256 + ((c ^ (r & 7)) << 4));
}
__device__ __forceinline__ uint32_t swzF(int r, int c) {   // 128B rows
    return (uint32_t)(r * 128 + ((c ^ (r & 7)) << 4));
}

// ---------------------------------------------------------------------------
// Megakernel prologue: LN partial sums -> (last arriver) stats -> weight
// conversion (hides the flag wait) -> spin -> normalize. Single launch.
// All 592 blocks are co-resident (4/SM), so the spin cannot deadlock.
// Deterministic: partials in per-chunk slots, fixed-order reduction.
// ---------------------------------------------------------------------------
__global__ void __launch_bounds__(256, 4)
mega_prep(const float* __restrict__ x, const float* __restrict__ g,
          const float* __restrict__ wq, const float* __restrict__ wkv,
          const float* __restrict__ wo) {
    const int bid = blockIdx.x, tid = threadIdx.x;
    const int NB = gridDim.x;

    // ---- Phase A: LN partial sums (blocks 0..127), slot per (b, chunk) ----
    if (bid < 128) {
        int d = (bid & 3) * 256 + tid;
        int c = (bid >> 2) & 15;
        int b = bid >> 6;
        const float* px = x + ((size_t)b * N_ + (size_t)c * CH_) * DIM_ + d;
        float s = 0.f, ss = 0.f;
#pragma unroll 4
        for (int n = 0; n < CH_; n++) {
            float v = px[(size_t)n * DIM_];
            s += v;
            ss += v * v;
        }
        size_t o = ((size_t)b * NCHUNK_ + c) * DIM_ + d;
        g_ps[o]  = s;
        g_pss[o] = ss;
        __threadfence();
    }
    __syncthreads();

    // ---- ticket: last arriver computes stats and raises the flag ----
    __shared__ int who;
    if (tid == 0) who = atomicAdd(&g_sync[0], 1);
    __syncthreads();
    if (who == NB - 1) {
        for (int i = tid; i < B_ * DIM_; i += 256) {
            int b = i >> 10, d = i & (DIM_ - 1);
            float s = 0.f, ss = 0.f;
#pragma unroll
            for (int c = 0; c < NCHUNK_; c++) {
                size_t o = ((size_t)b * NCHUNK_ + c) * DIM_ + d;
                s += g_ps[o];
                ss += g_pss[o];
            }
            float mean = s * (1.f / N_);
            float var  = fmaf(-mean, mean, ss * (1.f / N_));
            float sc   = rsqrtf(var + EPS_) * g[d];
            g_scale[i] = sc;
            g_bias[i]  = -mean * sc;
        }
        __threadfence();
        __syncthreads();
        if (tid == 0) atomicExch(&g_sync[1], 1);
    }

    // ---- Phase B: weight conversion (useful work while flag settles) ----
    constexpr int NQKV4 = DIM_ * QKVN_ / 4;            // 393216
    constexpr int NW4   = NQKV4 + INNER_ * DIM_ / 4;   // + 131072
    for (int i = bid * 256 + tid; i < NW4; i += NB * 256) {
        if (i < NQKV4) {
            int elem = i * 4;
            int row = elem / QKVN_, col = elem % QKVN_;
            float4 v;
            if (col < INNER_) {
                v = *reinterpret_cast<const float4*>(wq + (size_t)row * INNER_ + col);
                v.x *= QSCALE_; v.y *= QSCALE_; v.z *= QSCALE_; v.w *= QSCALE_;
            } else {
                v = *reinterpret_cast<const float4*>(
                    wkv + (size_t)row * (2 * INNER_) + col - INNER_);
            }
            uint2 u = {pack2h(v.x, v.y), pack2h(v.z, v.w)};
            reinterpret_cast<uint2*>(g_wqkv16)[i] = u;
        } else {
            int j = i - NQKV4;
            float4 v = reinterpret_cast<const float4*>(wo)[j];
            uint2 u = {pack2h(v.x, v.y), pack2h(v.z, v.w)};
            reinterpret_cast<uint2*>(g_wo16)[j] = u;
        }
    }

    // ---- spin for stats flag ----
    if (tid == 0) {
        while (atomicAdd(&g_sync[1], 0) == 0) __nanosleep(64);
    }
    __syncthreads();

    // ---- Phase D: normalize x -> fp16 (x hot in L2 from phase A) ----
    constexpr int NLN4 = B_ * N_ * DIM_ / 4;           // 2097152
    for (int i = bid * 256 + tid; i < NLN4; i += NB * 256) {
        int elem = i * 4;
        int d = elem & (DIM_ - 1);
        int b = elem / (N_ * DIM_);
        float4 xv = reinterpret_cast<const float4*>(x)[i];
        float4 sc = *reinterpret_cast<const float4*>(&g_scale[b * DIM_ + d]);
        float4 bi = *reinterpret_cast<const float4*>(&g_bias[b * DIM_ + d]);
        float rx = fmaf(xv.x, sc.x, bi.x);
        float ry = fmaf(xv.y, sc.y, bi.y);
        float rz = fmaf(xv.z, sc.z, bi.z);
        float rw = fmaf(xv.w, sc.w, bi.w);
        uint2 u = {pack2h(rx, ry), pack2h(rz, rw)};
        reinterpret_cast<uint2*>(g_xn16)[i] = u;
    }
}

// ---------------------------------------------------------------------------
// fp16 tensor-core GEMM, 3-stage cp.async, one sync per chunk.
// A single fp16, 1 MMA/logical, stage 16KB {A 0 | B 8192}.
// MODE 0: fp32 out. MODE 1: qkv epilogue (q | kv).
// ---------------------------------------------------------------------------
template <int MODE>
__global__ void __launch_bounds__(256, 2)
gemm_fp16(const __half* __restrict__ A, const __half* __restrict__ B,
          float* __restrict__ C, __half* __restrict__ Qout,
          __half* __restrict__ KV, int K, int N) {
    constexpr uint32_t STAGE = 16384u;
    constexpr uint32_t BOFF  = 8192u;
    extern __shared__ char sm_[];
    const uint32_t sb = smem_u32(sm_);
    const int tid = threadIdx.x, lane = tid & 31, w = tid >> 5;
    const int wm = w >> 1, wn = w & 1, g = lane >> 2, t4 = lane & 3;
    const int row0 = blockIdx.y * 128, col0 = blockIdx.x * 128;
    const int KT = K >> 5;

    const int ar = tid >> 2, ac = tid & 3;
    const int br = tid >> 4, bc = tid & 15;

    auto issue = [&](int kt) {
        const uint32_t st = sb + (uint32_t)(kt % 3) * STAGE;
        const __half* pa = A + (size_t)(row0 + ar) * K + kt * 32 + ac * 8;
        cp16(st + swzA(ar, ac), pa);
        cp16(st + swzA(ar + 64, ac), pa + (size_t)64 * K);
        const __half* pb = B + (size_t)(kt * 32 + br) * N + col0 + bc * 8;
        cp16(st + BOFF + swzB(br, bc), pb);
        cp16(st + BOFF + swzB(br + 16, bc), pb + (size_t)16 * N);
        cp_commit();
    };

    float acc[2][8][4];
#pragma unroll
    for (int mi = 0; mi < 2; mi++)
#pragma unroll
        for (int ni = 0; ni < 8; ni++)
#pragma unroll
            for (int j = 0; j < 4; j++) acc[mi][ni][j] = 0.f;

    issue(0);
    issue(1);
    for (int kt = 0; kt < KT; kt++) {
        cp_wait1();
        __syncthreads();
        const uint32_t st = sb + (uint32_t)(kt % 3) * STAGE;
#pragma unroll
        for (int kk = 0; kk < 2; kk++) {
            uint32_t aH[2][4];
            const int arow = 32 * wm + (lane & 15);
            const int ach  = 2 * kk + (lane >> 4);
#pragma unroll
            for (int mi = 0; mi < 2; mi++)
                ldm_x4(aH[mi], st + swzA(arow + 16 * mi, ach));
            const int brow = 16 * kk + (lane & 7) + ((lane >> 3) & 1) * 8;
#pragma unroll
            for (int nn = 0; nn < 4; nn++) {
                const int bch = 8 * wn + 2 * nn + (lane >> 4);
                uint32_t bh[4];
                ldm_x4_t(bh, st + BOFF + swzB(brow, bch));
#pragma unroll
                for (int sub = 0; sub < 2; sub++) {
                    const int ni = 2 * nn + sub;
#pragma unroll
                    for (int mi = 0; mi < 2; mi++)
                        mma16816(acc[mi][ni], aH[mi], bh + 2 * sub);
                }
            }
        }
        if (kt + 2 < KT) issue(kt + 2);
        else cp_commit();
    }

#pragma unroll
    for (int mi = 0; mi < 2; mi++) {
        int rA = row0 + 32 * wm + 16 * mi + g;
#pragma unroll
        for (int ni = 0; ni < 8; ni++) {
            int col = col0 + 64 * wn + 8 * ni + 2 * t4;
            if (MODE == 0) {
                float2 v0 = {acc[mi][ni][0], acc[mi][ni][1]};
                float2 v1 = {acc[mi][ni][2], acc[mi][ni][3]};
                *reinterpret_cast<float2*>(C + (size_t)rA * N + col) = v0;
                *reinterpret_cast<float2*>(C + (size_t)(rA + 8) * N + col) = v1;
            } else {
                if (col0 < INNER_) {
                    *reinterpret_cast<uint32_t*>(Qout + (size_t)rA * INNER_ + col) =
                        pack2h(acc[mi][ni][0], acc[mi][ni][1]);
                    *reinterpret_cast<uint32_t*>(Qout + (size_t)(rA + 8) * INNER_ + col) =
                        pack2h(acc[mi][ni][2], acc[mi][ni][3]);
                } else {
                    int ck = col - INNER_;
                    *reinterpret_cast<uint32_t*>(KV + (size_t)rA * (2 * INNER_) + ck) =
                        pack2h(acc[mi][ni][0], acc[mi][ni][1]);
                    *reinterpret_cast<uint32_t*>(KV + (size_t)(rA + 8) * (2 * INNER_) + ck) =
                        pack2h(acc[mi][ni][2], acc[mi][ni][3]);
                }
            }
        }
    }
}

// ---------------------------------------------------------------------------
// Flash attention (256 thr, 1 CTA/SM, 3-stage KV, split-KV across wn pair,
// shift-free softmax, base-2 fp16x2 exponentials). att stored single fp16.
// Smem: Q 16K | 3 KV stages x 32K | sL2 at 114688.
// ---------------------------------------------------------------------------
namespace { constexpr int FLASH_SMEM = 114688 + 512; }

__global__ void __launch_bounds__(256)
flash_kernel(const __half* __restrict__ q16, const __half* __restrict__ kv,
             __half* __restrict__ att) {
    extern __shared__ char sm_[];
    const uint32_t sb = smem_u32(sm_);
    float* sL2 = (float*)(sm_ + 114688);

    const int tid = threadIdx.x, lane = tid & 31, w = tid >> 5;
    const int wm = w >> 1, wn = w & 1, g = lane >> 2, t4 = lane & 3;
    const int qt = blockIdx.x, h = blockIdx.y, b = blockIdx.z;
    const size_t qrow0 = (size_t)(b * N_ + qt * 128);

    {
        int r = tid >> 3, c = tid & 7;
        const __half* pq = q16 + (qrow0 + r) * INNER_ + h * 64 + c * 8;
#pragma unroll
        for (int it = 0; it < 4; it++)
            cp16(sb + swzF(r + 32 * it, c), pq + (size_t)(32 * it) * INNER_);
    }

    auto issueKV = [&](int kt) {
        const uint32_t st = sb + 16384u + (uint32_t)(kt % 3) * 32768u;
        int r = tid >> 3, c = tid & 7;
        size_t rowb = (size_t)(b * N_ + kt * 128);
        const __half* pk = kv + (rowb + r) * (2 * INNER_) + h * 64 + c * 8;
#pragma unroll
        for (int it = 0; it < 4; it++) {
            uint32_t o = swzF(r + 32 * it, c);
            size_t go = (size_t)(32 * it) * (2 * INNER_);
            cp16(st + o,           pk + go);
            cp16(st + 16384u + o,  pk + go + 512);
        }
        cp_commit();
    };

    issueKV(0);
    issueKV(1);

    float o[2][8][4];
    float ls[2][2];
#pragma unroll
    for (int mi = 0; mi < 2; mi++) {
        ls[mi][0] = 0.f; ls[mi][1] = 0.f;
#pragma unroll
        for (int ni = 0; ni < 8; ni++)
#pragma unroll
            for (int j = 0; j < 4; j++) o[mi][ni][j] = 0.f;
    }

    for (int kt = 0; kt < 16; kt++) {
        cp_wait1();
        __syncthreads();
        const uint32_t st = sb + 16384u + (uint32_t)(kt % 3) * 32768u;

        float s[2][8][4];
#pragma unroll
        for (int mi = 0; mi < 2; mi++)
#pragma unroll
            for (int ni = 0; ni < 8; ni++)
#pragma unroll
                for (int j = 0; j < 4; j++) s[mi][ni][j] = 0.f;

#pragma unroll
        for (int kk = 0; kk < 4; kk++) {
            uint32_t aH[2][4];
            const int arow = 32 * wm + (lane & 15);
            const int ach  = 2 * kk + (lane >> 4);
#pragma unroll
            for (int mi = 0; mi < 2; mi++)
                ldm_x4(aH[mi], sb + swzF(arow + 16 * mi, ach));
            const int krw = (lane & 7) + (lane >> 4) * 8;
            const int kch = 2 * kk + ((lane >> 3) & 1);
#pragma unroll
            for (int nn = 0; nn < 4; nn++) {
                uint32_t bh[4];
                ldm_x4(bh, st + swzF(64 * wn + 16 * nn + krw, kch));
#pragma unroll
                for (int sub = 0; sub < 2; sub++) {
                    const int ni = 2 * nn + sub;
#pragma unroll
                    for (int mi = 0; mi < 2; mi++)
                        mma16816(s[mi][ni], aH[mi], bh + 2 * sub);
                }
            }
        }

        uint32_t P[2][8][2];
#pragma unroll
        for (int mi = 0; mi < 2; mi++)
#pragma unroll
            for (int ni = 0; ni < 8; ni++) {
                P[mi][ni][0] = ex2_2h(s[mi][ni][0], s[mi][ni][1]);
                P[mi][ni][1] = ex2_2h(s[mi][ni][2], s[mi][ni][3]);
                float2 f0 = __half22float2(
                    *reinterpret_cast<__half2*>(&P[mi][ni][0]));
                float2 f1 = __half22float2(
                    *reinterpret_cast<__half2*>(&P[mi][ni][1]));
                ls[mi][0] += f0.x + f0.y;
                ls[mi][1] += f1.x + f1.y;
            }

#pragma unroll
        for (int kk2 = 0; kk2 < 4; kk2++) {
            uint32_t aP[2][4];
#pragma unroll
            for (int mi = 0; mi < 2; mi++) {
                aP[mi][0] = P[mi][2 * kk2][0];
                aP[mi][1] = P[mi][2 * kk2][1];
                aP[mi][2] = P[mi][2 * kk2 + 1][0];
                aP[mi][3] = P[mi][2 * kk2 + 1][1];
            }
            const int vrw = 64 * wn + 16 * kk2 + (lane & 7) + ((lane >> 3) & 1) * 8;
#pragma unroll
            for (int nn = 0; nn < 4; nn++) {
                const int vch = 2 * nn + (lane >> 4);
                uint32_t bh[4];
                ldm_x4_t(bh, st + 16384u + swzF(vrw, vch));
#pragma unroll
                for (int sub = 0; sub < 2; sub++) {
                    const int ni = 2 * nn + sub;
#pragma unroll
                    for (int mi = 0; mi < 2; mi++)
                        mma16816(o[mi][ni], aP[mi], bh + 2 * sub);
                }
            }
        }

        if (kt + 2 < 16) issueKV(kt + 2);
        else cp_commit();
    }

#pragma unroll
    for (int mi = 0; mi < 2; mi++)
#pragma unroll
        for (int j = 0; j < 2; j++) {
            ls[mi][j] += __shfl_xor_sync(0xffffffffu, ls[mi][j], 1);
            ls[mi][j] += __shfl_xor_sync(0xffffffffu, ls[mi][j], 2);
        }

    __syncthreads();
    float* sO = (float*)(sm_);
    if (wn == 1) {
#pragma unroll
        for (int mi = 0; mi < 2; mi++) {
            int rA = 32 * wm + 16 * mi + g;
            if (t4 == 0) {
                sL2[rA]     = ls[mi][0];
                sL2[rA + 8] = ls[mi][1];
            }
#pragma unroll
            for (int ni = 0; ni < 8; ni++) {
                int d = 8 * ni + 2 * t4;
                sO[rA * 64 + d]           = o[mi][ni][0];
                sO[rA * 64 + d + 1]       = o[mi][ni][1];
                sO[(rA + 8) * 64 + d]     = o[mi][ni][2];
                sO[(rA + 8) * 64 + d + 1] = o[mi][ni][3];
            }
        }
    }
    __syncthreads();
    if (wn == 0) {
#pragma unroll
        for (int mi = 0; mi < 2; mi++) {
            int rA = 32 * wm + 16 * mi + g;
            int rB = rA + 8;
            float iA = 1.f / (ls[mi][0] + sL2[rA]);
            float iB = 1.f / (ls[mi][1] + sL2[rB]);
#pragma unroll
            for (int ni = 0; ni < 8; ni++) {
                int d = 8 * ni + 2 * t4;
                float v0 = (o[mi][ni][0] + sO[rA * 64 + d])     * iA;
                float v1 = (o[mi][ni][1] + sO[rA * 64 + d + 1]) * iA;
                float v2 = (o[mi][ni][2] + sO[rB * 64 + d])     * iB;
                float v3 = (o[mi][ni][3] + sO[rB * 64 + d + 1]) * iB;
                *reinterpret_cast<uint32_t*>(att + (qrow0 + rA) * INNER_ + h * 64 + d) =
                    pack2h(v0, v1);
                *reinterpret_cast<uint32_t*>(att + (qrow0 + rB) * INNER_ + h * 64 + d) =
                    pack2h(v2, v3);
            }
        }
    }
}

// ---------------------------------------------------------------------------
extern "C" void kernel_launch(void* const* d_in, const int* /*in_sizes*/,
                              int /*n_in*/, void* d_out, int /*out_size*/) {
    const float* x   = (const float*)d_in[0];
    const float* g   = (const float*)d_in[1];
    const float* wq  = (const float*)d_in[2];
    const float* wkv = (const float*)d_in[3];
    const float* wo  = (const float*)d_in[4];
    float* out = (float*)d_out;

    __half *xn, *q, *kv, *att, *wqkv, *wo16;
    int* syncp;
    cudaGetSymbolAddress((void**)&xn,    g_xn16);
    cudaGetSymbolAddress((void**)&q,     g_q16);
    cudaGetSymbolAddress((void**)&kv,    g_kv16);
    cudaGetSymbolAddress((void**)&att,   g_att16);
    cudaGetSymbolAddress((void**)&wqkv,  g_wqkv16);
    cudaGetSymbolAddress((void**)&wo16,  g_wo16);
    cudaGetSymbolAddress((void**)&syncp, g_sync);

    cudaFuncSetAttribute((const void*)gemm_fp16<1>,
                         cudaFuncAttributeMaxDynamicSharedMemorySize, 3 * 16384);
    cudaFuncSetAttribute((const void*)gemm_fp16<0>,
                         cudaFuncAttributeMaxDynamicSharedMemorySize, 3 * 16384);
    cudaFuncSetAttribute((const void*)flash_kernel,
                         cudaFuncAttributeMaxDynamicSharedMemorySize, FLASH_SMEM);

    // reset megakernel sync state (graph-replay safe)
    cudaMemsetAsync(syncp, 0, 2 * sizeof(int));

    // fused prologue: LN stats + normalize + weight conversion, one launch
    mega_prep<<<PREP_BLOCKS_, 256>>>(x, g, wq, wkv, wo);

    // fused qkv projection: [4096 x 1536]
    gemm_fp16<1><<<dim3(QKVN_ / 128, (B_ * N_) / 128), 256, 3 * 16384>>>(
        xn, wqkv, nullptr, q, kv, DIM_, QKVN_);

    // fused attention (split-KV flash, base-2 fp16x2 exp, att single fp16)
    flash_kernel<<<dim3(N_ / 128, HEADS_, B_), 256, FLASH_SMEM>>>(q, kv, att);

    // output projection: [4096 x 1024]
    gemm_fp16<0><<<dim3(DIM_ / 128, (B_ * N_) / 128), 256, 3 * 16384>>>(
        att, wo16, out, nullptr, nullptr, INNER_, DIM_);
}

// round 14
// speedup vs baseline: 1.0350x; 1.0350x over previous
#include <cuda_runtime.h>
#include <cuda_fp16.h>
#include <cstdint>

namespace {
constexpr int B_      = 2;
constexpr int N_      = 2048;
constexpr int DIM_    = 1024;
constexpr int HEADS_  = 8;
constexpr int DHEAD_  = 64;
constexpr int INNER_  = 512;
constexpr int QKVN_   = 1536;
constexpr float EPS_  = 1e-5f;
constexpr int NCHUNK_ = 16;
constexpr int CH_     = N_ / NCHUNK_;
constexpr float QSCALE_ = 0.125f * 1.4426950408889634f;  // 0.125 * log2(e)
}

// Scratch. ALL inter-kernel tensors single fp16.
__device__ __half g_xn16[B_ * N_ * DIM_];
__device__ __half g_q16 [B_ * N_ * INNER_];
__device__ __half g_kv16[B_ * N_ * 2 * INNER_];
__device__ __half g_att16[B_ * N_ * INNER_];
__device__ __half g_wqkv16[DIM_ * QKVN_];
__device__ __half g_wo16  [INNER_ * DIM_];
__device__ float g_ps [B_ * NCHUNK_ * DIM_];
__device__ float g_pss[B_ * NCHUNK_ * DIM_];
__device__ float g_scale[B_ * DIM_];
__device__ float g_bias [B_ * DIM_];

// ---------------------------------------------------------------------------
// Helpers
// ---------------------------------------------------------------------------
__device__ __forceinline__ uint32_t pack2h(float x, float y) {
    __half2 p = __halves2half2(__float2half_rn(x), __float2half_rn(y));
    return *reinterpret_cast<uint32_t*>(&p);
}
__device__ __forceinline__ uint32_t ex2_2h(float s0, float s1) {
    uint32_t r;
    asm("{\n.reg .b32 t;\n"
        "cvt.rn.f16x2.f32 t, %2, %1;\n"
        "ex2.approx.f16x2 %0, t;\n}"
        : "=r"(r) : "f"(s0), "f"(s1));
    return r;
}

__device__ __forceinline__ void mma16816(float* c, const uint32_t* a, const uint32_t* b) {
    asm volatile(
        "mma.sync.aligned.m16n8k16.row.col.f32.f16.f16.f32 "
        "{%0,%1,%2,%3},{%4,%5,%6,%7},{%8,%9},{%0,%1,%2,%3};\n"
        : "+f"(c[0]), "+f"(c[1]), "+f"(c[2]), "+f"(c[3])
        : "r"(a[0]), "r"(a[1]), "r"(a[2]), "r"(a[3]), "r"(b[0]), "r"(b[1]));
}

__device__ __forceinline__ uint32_t smem_u32(const void* p) {
    return (uint32_t)__cvta_generic_to_shared(p);
}
__device__ __forceinline__ void ldm_x4(uint32_t* r, uint32_t a) {
    asm volatile("ldmatrix.sync.aligned.m8n8.x4.shared.b16 {%0,%1,%2,%3},[%4];"
                 : "=r"(r[0]), "=r"(r[1]), "=r"(r[2]), "=r"(r[3]) : "r"(a));
}
__device__ __forceinline__ void ldm_x4_t(uint32_t* r, uint32_t a) {
    asm volatile("ldmatrix.sync.aligned.m8n8.x4.trans.shared.b16 {%0,%1,%2,%3},[%4];"
                 : "=r"(r[0]), "=r"(r[1]), "=r"(r[2]), "=r"(r[3]) : "r"(a));
}
__device__ __forceinline__ void cp16(uint32_t dst, const void* src) {
    asm volatile("cp.async.cg.shared.global [%0],[%1],16;\n" :: "r"(dst), "l"(src));
}
__device__ __forceinline__ void cp_commit() {
    asm volatile("cp.async.commit_group;\n" ::: "memory");
}
__device__ __forceinline__ void cp_wait1() {
    asm volatile("cp.async.wait_group 1;\n" ::: "memory");
}

// Swizzles (16B chunk granularity)
__device__ __forceinline__ uint32_t swzA(int r, int c) {   // 64B rows
    return (uint32_t)(r * 64 + ((c ^ ((r >> 1) & 3)) << 4));
}
__device__ __forceinline__ uint32_t swzB(int r, int c) {   // 256B rows
    return (uint32_t)(r * 256 + ((c ^ (r & 7)) << 4));
}
__device__ __forceinline__ uint32_t swzF(int r, int c) {   // 128B rows
    return (uint32_t)(r * 128 + ((c ^ (r & 7)) << 4));
}

// ---------------------------------------------------------------------------
// LayerNorm over sequence axis (axis=1)
// ---------------------------------------------------------------------------
__global__ void ln_partial_kernel(const float* __restrict__ x) {
    int d = blockIdx.x * blockDim.x + threadIdx.x;
    int c = blockIdx.y;
    int b = blockIdx.z;
    const float* px = x + ((size_t)b * N_ + (size_t)c * CH_) * DIM_ + d;
    float s = 0.f, ss = 0.f;
#pragma unroll 4
    for (int n = 0; n < CH_; n++) {
        float v = px[(size_t)n * DIM_];
        s += v;
        ss += v * v;
    }
    size_t o = ((size_t)b * NCHUNK_ + c) * DIM_ + d;
    g_ps[o]  = s;
    g_pss[o] = ss;
}

__global__ void ln_stats_kernel(const float* __restrict__ g) {
    int d = blockIdx.x * blockDim.x + threadIdx.x;
    int b = blockIdx.z;
    float s = 0.f, ss = 0.f;
#pragma unroll
    for (int c = 0; c < NCHUNK_; c++) {
        size_t o = ((size_t)b * NCHUNK_ + c) * DIM_ + d;
        s += g_ps[o];
        ss += g_pss[o];
    }
    float mean = s * (1.f / N_);
    float var  = fmaf(-mean, mean, ss * (1.f / N_));
    float sc   = rsqrtf(var + EPS_) * g[d];
    g_scale[b * DIM_ + d] = sc;
    g_bias[b * DIM_ + d]  = -mean * sc;
}

// ---------------------------------------------------------------------------
// Fused: LN normalize (-> single fp16) + weight conversion. One launch.
// q columns carry 0.125 * log2(e) so QK scores are in log2 domain.
// ---------------------------------------------------------------------------
__global__ void prep_kernel(const float* __restrict__ x,
                            const float* __restrict__ wq,
                            const float* __restrict__ wkv,
                            const float* __restrict__ wo) {
    constexpr int NLN = (B_ * N_ * DIM_ / 4) / 256;
    constexpr int NQKV4 = DIM_ * QKVN_ / 4;
    if (blockIdx.x < NLN) {
        int i = blockIdx.x * blockDim.x + threadIdx.x;
        int elem = i * 4;
        int d = elem & (DIM_ - 1);
        int b = elem / (N_ * DIM_);
        float4 xv = reinterpret_cast<const float4*>(x)[i];
        float4 sc = *reinterpret_cast<const float4*>(&g_scale[b * DIM_ + d]);
        float4 bi = *reinterpret_cast<const float4*>(&g_bias[b * DIM_ + d]);
        float rx = fmaf(xv.x, sc.x, bi.x);
        float ry = fmaf(xv.y, sc.y, bi.y);
        float rz = fmaf(xv.z, sc.z, bi.z);
        float rw = fmaf(xv.w, sc.w, bi.w);
        uint2 u = {pack2h(rx, ry), pack2h(rz, rw)};
        reinterpret_cast<uint2*>(g_xn16)[i] = u;
    } else {
        int i = (blockIdx.x - NLN) * blockDim.x + threadIdx.x;
        if (i < NQKV4) {
            int elem = i * 4;
            int row = elem / QKVN_, col = elem % QKVN_;
            float4 v;
            if (col < INNER_) {
                v = *reinterpret_cast<const float4*>(wq + (size_t)row * INNER_ + col);
                v.x *= QSCALE_; v.y *= QSCALE_; v.z *= QSCALE_; v.w *= QSCALE_;
            } else {
                v = *reinterpret_cast<const float4*>(
                    wkv + (size_t)row * (2 * INNER_) + col - INNER_);
            }
            uint2 u = {pack2h(v.x, v.y), pack2h(v.z, v.w)};
            reinterpret_cast<uint2*>(g_wqkv16)[i] = u;
        } else {
            int j = i - NQKV4;
            float4 v = reinterpret_cast<const float4*>(wo)[j];
            uint2 u = {pack2h(v.x, v.y), pack2h(v.z, v.w)};
            reinterpret_cast<uint2*>(g_wo16)[j] = u;
        }
    }
}

// ---------------------------------------------------------------------------
// qkv GEMM: BK=32, 3-stage cp.async, one sync per chunk (at HMMA floor).
// Stage 16KB {A 0 | B 8192}. Epilogue: q | kv fp16.
// ---------------------------------------------------------------------------
__global__ void __launch_bounds__(256, 2)
gemm_qkv(const __half* __restrict__ A, const __half* __restrict__ B,
         __half* __restrict__ Qout, __half* __restrict__ KV, int K, int N) {
    constexpr uint32_t STAGE = 16384u;
    constexpr uint32_t BOFF  = 8192u;
    extern __shared__ char sm_[];
    const uint32_t sb = smem_u32(sm_);
    const int tid = threadIdx.x, lane = tid & 31, w = tid >> 5;
    const int wm = w >> 1, wn = w & 1, g = lane >> 2, t4 = lane & 3;
    const int row0 = blockIdx.y * 128, col0 = blockIdx.x * 128;
    const int KT = K >> 5;

    const int ar = tid >> 2, ac = tid & 3;
    const int br = tid >> 4, bc = tid & 15;

    auto issue = [&](int kt) {
        const uint32_t st = sb + (uint32_t)(kt % 3) * STAGE;
        const __half* pa = A + (size_t)(row0 + ar) * K + kt * 32 + ac * 8;
        cp16(st + swzA(ar, ac), pa);
        cp16(st + swzA(ar + 64, ac), pa + (size_t)64 * K);
        const __half* pb = B + (size_t)(kt * 32 + br) * N + col0 + bc * 8;
        cp16(st + BOFF + swzB(br, bc), pb);
        cp16(st + BOFF + swzB(br + 16, bc), pb + (size_t)16 * N);
        cp_commit();
    };

    float acc[2][8][4];
#pragma unroll
    for (int mi = 0; mi < 2; mi++)
#pragma unroll
        for (int ni = 0; ni < 8; ni++)
#pragma unroll
            for (int j = 0; j < 4; j++) acc[mi][ni][j] = 0.f;

    issue(0);
    issue(1);
    for (int kt = 0; kt < KT; kt++) {
        cp_wait1();
        __syncthreads();
        const uint32_t st = sb + (uint32_t)(kt % 3) * STAGE;
#pragma unroll
        for (int kk = 0; kk < 2; kk++) {
            uint32_t aH[2][4];
            const int arow = 32 * wm + (lane & 15);
            const int ach  = 2 * kk + (lane >> 4);
#pragma unroll
            for (int mi = 0; mi < 2; mi++)
                ldm_x4(aH[mi], st + swzA(arow + 16 * mi, ach));
            const int brow = 16 * kk + (lane & 7) + ((lane >> 3) & 1) * 8;
#pragma unroll
            for (int nn = 0; nn < 4; nn++) {
                const int bch = 8 * wn + 2 * nn + (lane >> 4);
                uint32_t bh[4];
                ldm_x4_t(bh, st + BOFF + swzB(brow, bch));
#pragma unroll
                for (int sub = 0; sub < 2; sub++) {
                    const int ni = 2 * nn + sub;
#pragma unroll
                    for (int mi = 0; mi < 2; mi++)
                        mma16816(acc[mi][ni], aH[mi], bh + 2 * sub);
                }
            }
        }
        if (kt + 2 < KT) issue(kt + 2);
        else cp_commit();
    }

#pragma unroll
    for (int mi = 0; mi < 2; mi++) {
        int rA = row0 + 32 * wm + 16 * mi + g;
#pragma unroll
        for (int ni = 0; ni < 8; ni++) {
            int col = col0 + 64 * wn + 8 * ni + 2 * t4;
            if (col0 < INNER_) {
                *reinterpret_cast<uint32_t*>(Qout + (size_t)rA * INNER_ + col) =
                    pack2h(acc[mi][ni][0], acc[mi][ni][1]);
                *reinterpret_cast<uint32_t*>(Qout + (size_t)(rA + 8) * INNER_ + col) =
                    pack2h(acc[mi][ni][2], acc[mi][ni][3]);
            } else {
                int ck = col - INNER_;
                *reinterpret_cast<uint32_t*>(KV + (size_t)rA * (2 * INNER_) + ck) =
                    pack2h(acc[mi][ni][0], acc[mi][ni][1]);
                *reinterpret_cast<uint32_t*>(KV + (size_t)(rA + 8) * (2 * INNER_) + ck) =
                    pack2h(acc[mi][ni][2], acc[mi][ni][3]);
            }
        }
    }
}

// ---------------------------------------------------------------------------
// Output GEMM: BK=64 chunks (8 chunks for K=512 -> half the sync rounds),
// 3-stage cp.async at 32KB/stage (96KB, still 2 CTAs/SM). fp32 out.
// Same global k-order as BK=32 version -> bitwise identical accumulation.
// Stage: A 16KB (128 rows x 128B, swzF) | B 16KB at 16384 (64 rows x 256B, swzB).
// ---------------------------------------------------------------------------
namespace { constexpr int OUT_SMEM = 3 * 32768; }

__global__ void __launch_bounds__(256, 2)
gemm_out(const __half* __restrict__ A, const __half* __restrict__ B,
         float* __restrict__ C, int K, int N) {
    extern __shared__ char sm_[];
    const uint32_t sb = smem_u32(sm_);
    const int tid = threadIdx.x, lane = tid & 31, w = tid >> 5;
    const int wm = w >> 1, wn = w & 1, g = lane >> 2, t4 = lane & 3;
    const int row0 = blockIdx.y * 128, col0 = blockIdx.x * 128;
    const int KT = K >> 6;   // 64-wide chunks

    const int ar = tid >> 3, ac = tid & 7;     // A: 32 rows/iter x 8 chunks
    const int br = tid >> 4, bc = tid & 15;    // B: 16 rows/iter x 16 chunks

    auto issue = [&](int kt) {
        const uint32_t st = sb + (uint32_t)(kt % 3) * 32768u;
        const __half* pa = A + (size_t)(row0 + ar) * K + kt * 64 + ac * 8;
#pragma unroll
        for (int it = 0; it < 4; it++)
            cp16(st + swzF(ar + 32 * it, ac), pa + (size_t)(32 * it) * K);
        const __half* pb = B + (size_t)(kt * 64 + br) * N + col0 + bc * 8;
#pragma unroll
        for (int it = 0; it < 4; it++)
            cp16(st + 16384u + swzB(br + 16 * it, bc), pb + (size_t)(16 * it) * N);
        cp_commit();
    };

    float acc[2][8][4];
#pragma unroll
    for (int mi = 0; mi < 2; mi++)
#pragma unroll
        for (int ni = 0; ni < 8; ni++)
#pragma unroll
            for (int j = 0; j < 4; j++) acc[mi][ni][j] = 0.f;

    issue(0);
    issue(1);
    for (int kt = 0; kt < KT; kt++) {
        cp_wait1();
        __syncthreads();
        const uint32_t st = sb + (uint32_t)(kt % 3) * 32768u;
#pragma unroll
        for (int kk = 0; kk < 4; kk++) {
            uint32_t aH[2][4];
            const int arow = 32 * wm + (lane & 15);
            const int ach  = 2 * kk + (lane >> 4);
#pragma unroll
            for (int mi = 0; mi < 2; mi++)
                ldm_x4(aH[mi], st + swzF(arow + 16 * mi, ach));
            const int brow = 16 * kk + (lane & 7) + ((lane >> 3) & 1) * 8;
#pragma unroll
            for (int nn = 0; nn < 4; nn++) {
                const int bch = 8 * wn + 2 * nn + (lane >> 4);
                uint32_t bh[4];
                ldm_x4_t(bh, st + 16384u + swzB(brow, bch));
#pragma unroll
                for (int sub = 0; sub < 2; sub++) {
                    const int ni = 2 * nn + sub;
#pragma unroll
                    for (int mi = 0; mi < 2; mi++)
                        mma16816(acc[mi][ni], aH[mi], bh + 2 * sub);
                }
            }
        }
        if (kt + 2 < KT) issue(kt + 2);
        else cp_commit();
    }

#pragma unroll
    for (int mi = 0; mi < 2; mi++) {
        int rA = row0 + 32 * wm + 16 * mi + g;
#pragma unroll
        for (int ni = 0; ni < 8; ni++) {
            int col = col0 + 64 * wn + 8 * ni + 2 * t4;
            float2 v0 = {acc[mi][ni][0], acc[mi][ni][1]};
            float2 v1 = {acc[mi][ni][2], acc[mi][ni][3]};
            *reinterpret_cast<float2*>(C + (size_t)rA * N + col) = v0;
            *reinterpret_cast<float2*>(C + (size_t)(rA + 8) * N + col) = v1;
        }
    }
}

// ---------------------------------------------------------------------------
// Flash attention (256 thr, 1 CTA/SM, 3-stage KV, split-KV across wn pair,
// shift-free softmax, base-2 fp16x2 exponentials). att stored single fp16.
// Smem: Q 16K | 3 KV stages x 32K | sL2 at 114688.
// ---------------------------------------------------------------------------
namespace { constexpr int FLASH_SMEM = 114688 + 512; }

__global__ void __launch_bounds__(256)
flash_kernel(const __half* __restrict__ q16, const __half* __restrict__ kv,
             __half* __restrict__ att) {
    extern __shared__ char sm_[];
    const uint32_t sb = smem_u32(sm_);
    float* sL2 = (float*)(sm_ + 114688);

    const int tid = threadIdx.x, lane = tid & 31, w = tid >> 5;
    const int wm = w >> 1, wn = w & 1, g = lane >> 2, t4 = lane & 3;
    const int qt = blockIdx.x, h = blockIdx.y, b = blockIdx.z;
    const size_t qrow0 = (size_t)(b * N_ + qt * 128);

    {
        int r = tid >> 3, c = tid & 7;
        const __half* pq = q16 + (qrow0 + r) * INNER_ + h * 64 + c * 8;
#pragma unroll
        for (int it = 0; it < 4; it++)
            cp16(sb + swzF(r + 32 * it, c), pq + (size_t)(32 * it) * INNER_);
    }

    auto issueKV = [&](int kt) {
        const uint32_t st = sb + 16384u + (uint32_t)(kt % 3) * 32768u;
        int r = tid >> 3, c = tid & 7;
        size_t rowb = (size_t)(b * N_ + kt * 128);
        const __half* pk = kv + (rowb + r) * (2 * INNER_) + h * 64 + c * 8;
#pragma unroll
        for (int it = 0; it < 4; it++) {
            uint32_t o = swzF(r + 32 * it, c);
            size_t go = (size_t)(32 * it) * (2 * INNER_);
            cp16(st + o,           pk + go);
            cp16(st + 16384u + o,  pk + go + 512);
        }
        cp_commit();
    };

    issueKV(0);
    issueKV(1);

    float o[2][8][4];
    float ls[2][2];
#pragma unroll
    for (int mi = 0; mi < 2; mi++) {
        ls[mi][0] = 0.f; ls[mi][1] = 0.f;
#pragma unroll
        for (int ni = 0; ni < 8; ni++)
#pragma unroll
            for (int j = 0; j < 4; j++) o[mi][ni][j] = 0.f;
    }

    for (int kt = 0; kt < 16; kt++) {
        cp_wait1();
        __syncthreads();
        const uint32_t st = sb + 16384u + (uint32_t)(kt % 3) * 32768u;

        float s[2][8][4];
#pragma unroll
        for (int mi = 0; mi < 2; mi++)
#pragma unroll
            for (int ni = 0; ni < 8; ni++)
#pragma unroll
                for (int j = 0; j < 4; j++) s[mi][ni][j] = 0.f;

#pragma unroll
        for (int kk = 0; kk < 4; kk++) {
            uint32_t aH[2][4];
            const int arow = 32 * wm + (lane & 15);
            const int ach  = 2 * kk + (lane >> 4);
#pragma unroll
            for (int mi = 0; mi < 2; mi++)
                ldm_x4(aH[mi], sb + swzF(arow + 16 * mi, ach));
            const int krw = (lane & 7) + (lane >> 4) * 8;
            const int kch = 2 * kk + ((lane >> 3) & 1);
#pragma unroll
            for (int nn = 0; nn < 4; nn++) {
                uint32_t bh[4];
                ldm_x4(bh, st + swzF(64 * wn + 16 * nn + krw, kch));
#pragma unroll
                for (int sub = 0; sub < 2; sub++) {
                    const int ni = 2 * nn + sub;
#pragma unroll
                    for (int mi = 0; mi < 2; mi++)
                        mma16816(s[mi][ni], aH[mi], bh + 2 * sub);
                }
            }
        }

        uint32_t P[2][8][2];
#pragma unroll
        for (int mi = 0; mi < 2; mi++)
#pragma unroll
            for (int ni = 0; ni < 8; ni++) {
                P[mi][ni][0] = ex2_2h(s[mi][ni][0], s[mi][ni][1]);
                P[mi][ni][1] = ex2_2h(s[mi][ni][2], s[mi][ni][3]);
                float2 f0 = __half22float2(
                    *reinterpret_cast<__half2*>(&P[mi][ni][0]));
                float2 f1 = __half22float2(
                    *reinterpret_cast<__half2*>(&P[mi][ni][1]));
                ls[mi][0] += f0.x + f0.y;
                ls[mi][1] += f1.x + f1.y;
            }

#pragma unroll
        for (int kk2 = 0; kk2 < 4; kk2++) {
            uint32_t aP[2][4];
#pragma unroll
            for (int mi = 0; mi < 2; mi++) {
                aP[mi][0] = P[mi][2 * kk2][0];
                aP[mi][1] = P[mi][2 * kk2][1];
                aP[mi][2] = P[mi][2 * kk2 + 1][0];
                aP[mi][3] = P[mi][2 * kk2 + 1][1];
            }
            const int vrw = 64 * wn + 16 * kk2 + (lane & 7) + ((lane >> 3) & 1) * 8;
#pragma unroll
            for (int nn = 0; nn < 4; nn++) {
                const int vch = 2 * nn + (lane >> 4);
                uint32_t bh[4];
                ldm_x4_t(bh, st + 16384u + swzF(vrw, vch));
#pragma unroll
                for (int sub = 0; sub < 2; sub++) {
                    const int ni = 2 * nn + sub;
#pragma unroll
                    for (int mi = 0; mi < 2; mi++)
                        mma16816(o[mi][ni], aP[mi], bh + 2 * sub);
                }
            }
        }

        if (kt + 2 < 16) issueKV(kt + 2);
        else cp_commit();
    }

#pragma unroll
    for (int mi = 0; mi < 2; mi++)
#pragma unroll
        for (int j = 0; j < 2; j++) {
            ls[mi][j] += __shfl_xor_sync(0xffffffffu, ls[mi][j], 1);
            ls[mi][j] += __shfl_xor_sync(0xffffffffu, ls[mi][j], 2);
        }

    __syncthreads();
    float* sO = (float*)(sm_);
    if (wn == 1) {
#pragma unroll
        for (int mi = 0; mi < 2; mi++) {
            int rA = 32 * wm + 16 * mi + g;
            if (t4 == 0) {
                sL2[rA]     = ls[mi][0];
                sL2[rA + 8] = ls[mi][1];
            }
#pragma unroll
            for (int ni = 0; ni < 8; ni++) {
                int d = 8 * ni + 2 * t4;
                sO[rA * 64 + d]           = o[mi][ni][0];
                sO[rA * 64 + d + 1]       = o[mi][ni][1];
                sO[(rA + 8) * 64 + d]     = o[mi][ni][2];
                sO[(rA + 8) * 64 + d + 1] = o[mi][ni][3];
            }
        }
    }
    __syncthreads();
    if (wn == 0) {
#pragma unroll
        for (int mi = 0; mi < 2; mi++) {
            int rA = 32 * wm + 16 * mi + g;
            int rB = rA + 8;
            float iA = 1.f / (ls[mi][0] + sL2[rA]);
            float iB = 1.f / (ls[mi][1] + sL2[rB]);
#pragma unroll
            for (int ni = 0; ni < 8; ni++) {
                int d = 8 * ni + 2 * t4;
                float v0 = (o[mi][ni][0] + sO[rA * 64 + d])     * iA;
                float v1 = (o[mi][ni][1] + sO[rA * 64 + d + 1]) * iA;
                float v2 = (o[mi][ni][2] + sO[rB * 64 + d])     * iB;
                float v3 = (o[mi][ni][3] + sO[rB * 64 + d + 1]) * iB;
                *reinterpret_cast<uint32_t*>(att + (qrow0 + rA) * INNER_ + h * 64 + d) =
                    pack2h(v0, v1);
                *reinterpret_cast<uint32_t*>(att + (qrow0 + rB) * INNER_ + h * 64 + d) =
                    pack2h(v2, v3);
            }
        }
    }
}

// ---------------------------------------------------------------------------
extern "C" void kernel_launch(void* const* d_in, const int* /*in_sizes*/,
                              int /*n_in*/, void* d_out, int /*out_size*/) {
    const float* x   = (const float*)d_in[0];
    const float* g   = (const float*)d_in[1];
    const float* wq  = (const float*)d_in[2];
    const float* wkv = (const float*)d_in[3];
    const float* wo  = (const float*)d_in[4];
    float* out = (float*)d_out;

    __half *xn, *q, *kv, *att, *wqkv, *wo16;
    cudaGetSymbolAddress((void**)&xn,   g_xn16);
    cudaGetSymbolAddress((void**)&q,    g_q16);
    cudaGetSymbolAddress((void**)&kv,   g_kv16);
    cudaGetSymbolAddress((void**)&att,  g_att16);
    cudaGetSymbolAddress((void**)&wqkv, g_wqkv16);
    cudaGetSymbolAddress((void**)&wo16, g_wo16);

    cudaFuncSetAttribute((const void*)gemm_qkv,
                         cudaFuncAttributeMaxDynamicSharedMemorySize, 3 * 16384);
    cudaFuncSetAttribute((const void*)gemm_out,
                         cudaFuncAttributeMaxDynamicSharedMemorySize, OUT_SMEM);
    cudaFuncSetAttribute((const void*)flash_kernel,
                         cudaFuncAttributeMaxDynamicSharedMemorySize, FLASH_SMEM);

    // LayerNorm stats (sequence-axis)
    ln_partial_kernel<<<dim3(DIM_ / 256, NCHUNK_, B_), 256>>>(x);
    ln_stats_kernel<<<dim3(DIM_ / 256, 1, B_), 256>>>(g);

    // fused: LN normalize + weight conversion (q scale * log2e folded)
    constexpr int PREP_BLOCKS =
        (B_ * N_ * DIM_ / 4) / 256 + ((DIM_ * QKVN_ + INNER_ * DIM_) / 4) / 256;
    prep_kernel<<<PREP_BLOCKS, 256>>>(x, wq, wkv, wo);

    // fused qkv projection: [4096 x 1536]
    gemm_qkv<<<dim3(QKVN_ / 128, (B_ * N_) / 128), 256, 3 * 16384>>>(
        xn, wqkv, q, kv, DIM_, QKVN_);

    // fused attention (split-KV flash, base-2 fp16x2 exp, att single fp16)
    flash_kernel<<<dim3(N_ / 128, HEADS_, B_), 256, FLASH_SMEM>>>(q, kv, att);

    // output projection: [4096 x 1024], BK=64 chunks
    gemm_out<<<dim3(DIM_ / 128, (B_ * N_) / 128), 256, OUT_SMEM>>>(
        att, wo16, out, INNER_, DIM_);
}

// round 15
// speedup vs baseline: 1.0703x; 1.0341x over previous
#include <cuda_runtime.h>
#include <cuda_fp16.h>
#include <cstdint>

namespace {
constexpr int B_      = 2;
constexpr int N_      = 2048;
constexpr int DIM_    = 1024;
constexpr int HEADS_  = 8;
constexpr int DHEAD_  = 64;
constexpr int INNER_  = 512;
constexpr int QKVN_   = 1536;
constexpr float EPS_  = 1e-5f;
constexpr int NCHUNK_ = 16;
constexpr int CH_     = N_ / NCHUNK_;
constexpr float QSCALE_ = 0.125f * 1.4426950408889634f;  // 0.125 * log2(e)
}

// Scratch. ALL inter-kernel tensors single fp16.
__device__ __half g_xn16[B_ * N_ * DIM_];
__device__ __half g_q16 [B_ * N_ * INNER_];
__device__ __half g_kv16[B_ * N_ * 2 * INNER_];
__device__ __half g_att16[B_ * N_ * INNER_];
__device__ __half g_wqkv16[DIM_ * QKVN_];
__device__ __half g_wo16  [INNER_ * DIM_];
__device__ float g_ps [B_ * NCHUNK_ * DIM_];
__device__ float g_pss[B_ * NCHUNK_ * DIM_];
__device__ float g_scale[B_ * DIM_];
__device__ float g_bias [B_ * DIM_];

// ---------------------------------------------------------------------------
// Helpers
// ---------------------------------------------------------------------------
__device__ __forceinline__ uint32_t pack2h(float x, float y) {
    __half2 p = __halves2half2(__float2half_rn(x), __float2half_rn(y));
    return *reinterpret_cast<uint32_t*>(&p);
}
__device__ __forceinline__ uint32_t ex2_2h(float s0, float s1) {
    uint32_t r;
    asm("{\n.reg .b32 t;\n"
        "cvt.rn.f16x2.f32 t, %2, %1;\n"
        "ex2.approx.f16x2 %0, t;\n}"
        : "=r"(r) : "f"(s0), "f"(s1));
    return r;
}

__device__ __forceinline__ void mma16816(float* c, const uint32_t* a, const uint32_t* b) {
    asm volatile(
        "mma.sync.aligned.m16n8k16.row.col.f32.f16.f16.f32 "
        "{%0,%1,%2,%3},{%4,%5,%6,%7},{%8,%9},{%0,%1,%2,%3};\n"
        : "+f"(c[0]), "+f"(c[1]), "+f"(c[2]), "+f"(c[3])
        : "r"(a[0]), "r"(a[1]), "r"(a[2]), "r"(a[3]), "r"(b[0]), "r"(b[1]));
}

__device__ __forceinline__ uint32_t smem_u32(const void* p) {
    return (uint32_t)__cvta_generic_to_shared(p);
}
__device__ __forceinline__ void ldm_x4(uint32_t* r, uint32_t a) {
    asm volatile("ldmatrix.sync.aligned.m8n8.x4.shared.b16 {%0,%1,%2,%3},[%4];"
                 : "=r"(r[0]), "=r"(r[1]), "=r"(r[2]), "=r"(r[3]) : "r"(a));
}
__device__ __forceinline__ void ldm_x4_t(uint32_t* r, uint32_t a) {
    asm volatile("ldmatrix.sync.aligned.m8n8.x4.trans.shared.b16 {%0,%1,%2,%3},[%4];"
                 : "=r"(r[0]), "=r"(r[1]), "=r"(r[2]), "=r"(r[3]) : "r"(a));
}
__device__ __forceinline__ void cp16(uint32_t dst, const void* src) {
    asm volatile("cp.async.cg.shared.global [%0],[%1],16;\n" :: "r"(dst), "l"(src));
}
__device__ __forceinline__ void cp_commit() {
    asm volatile("cp.async.commit_group;\n" ::: "memory");
}
__device__ __forceinline__ void cp_wait1() {
    asm volatile("cp.async.wait_group 1;\n" ::: "memory");
}

// Swizzles (16B chunk granularity)
__device__ __forceinline__ uint32_t swzA(int r, int c) {   // 64B rows
    return (uint32_t)(r * 64 + ((c ^ ((r >> 1) & 3)) << 4));
}
__device__ __forceinline__ uint32_t swzB(int r, int c) {   // 256B rows
    return (uint32_t)(r * 256 + ((c ^ (r & 7)) << 4));
}
__device__ __forceinline__ uint32_t swzF(int r, int c) {   // 128B rows
    return (uint32_t)(r * 128 + ((c ^ (r & 7)) << 4));
}

// ---------------------------------------------------------------------------
// LayerNorm over sequence axis: partial sums. 2 independent accumulator
// pairs break the serial FADD chain; loads front-batch (MLP 4).
// Same slot values as before (pairwise order change is exact for fp add of
// the same values? NO - fp add is order sensitive; keep ORIGINAL order).
// NOTE: accumulation order preserved exactly: s = ((v0+v1)+v2)+... original
// was strictly sequential; to keep bitwise-identical stats we retain the
// sequential order but unroll deeper so LDGs batch (adds stay chained, the
// loads are what stall). MLP comes from the unrolled loads, not the adds.
// ---------------------------------------------------------------------------
__global__ void ln_partial_kernel(const float* __restrict__ x) {
    int d = blockIdx.x * blockDim.x + threadIdx.x;
    int c = blockIdx.y;
    int b = blockIdx.z;
    const float* px = x + ((size_t)b * N_ + (size_t)c * CH_) * DIM_ + d;
    float s = 0.f, ss = 0.f;
#pragma unroll
    for (int n0 = 0; n0 < CH_; n0 += 8) {
        float v[8];
#pragma unroll
        for (int u = 0; u < 8; u++) v[u] = px[(size_t)(n0 + u) * DIM_];
#pragma unroll
        for (int u = 0; u < 8; u++) {
            s += v[u];
            ss += v[u] * v[u];
        }
    }
    size_t o = ((size_t)b * NCHUNK_ + c) * DIM_ + d;
    g_ps[o]  = s;
    g_pss[o] = ss;
}

__global__ void ln_stats_kernel(const float* __restrict__ g) {
    int d = blockIdx.x * blockDim.x + threadIdx.x;
    int b = blockIdx.z;
    float s = 0.f, ss = 0.f;
#pragma unroll
    for (int c = 0; c < NCHUNK_; c++) {
        size_t o = ((size_t)b * NCHUNK_ + c) * DIM_ + d;
        s += g_ps[o];
        ss += g_pss[o];
    }
    float mean = s * (1.f / N_);
    float var  = fmaf(-mean, mean, ss * (1.f / N_));
    float sc   = rsqrtf(var + EPS_) * g[d];
    g_scale[b * DIM_ + d] = sc;
    g_bias[b * DIM_ + d]  = -mean * sc;
}

// ---------------------------------------------------------------------------
// Fused: LN normalize (-> single fp16) + weight conversion, MLP=4 version.
// Each thread handles 4 grid-strided float4s; all loads issued before any
// convert/store. Per-element math identical to the R14 version.
// ---------------------------------------------------------------------------
__global__ void prep_kernel(const float* __restrict__ x,
                            const float* __restrict__ wq,
                            const float* __restrict__ wkv,
                            const float* __restrict__ wo) {
    constexpr int NLN4  = B_ * N_ * DIM_ / 4;            // 2097152 float4
    constexpr int LNB   = 2048;                          // LN blocks
    constexpr int LNT   = LNB * 256;                     // 524288 threads
    constexpr int NQKV4 = DIM_ * QKVN_ / 4;              // 393216
    constexpr int NW4   = NQKV4 + INNER_ * DIM_ / 4;     // 524288
    constexpr int CVT   = 512 * 256;                     // 131072 threads

    const int tid = threadIdx.x;
    if (blockIdx.x < LNB) {
        const int t = blockIdx.x * 256 + tid;
        float4 xv[4];
#pragma unroll
        for (int u = 0; u < 4; u++)
            xv[u] = reinterpret_cast<const float4*>(x)[t + u * LNT];
#pragma unroll
        for (int u = 0; u < 4; u++) {
            int i = t + u * LNT;
            int elem = i * 4;
            int d = elem & (DIM_ - 1);
            int b = elem / (N_ * DIM_);
            float4 sc = *reinterpret_cast<const float4*>(&g_scale[b * DIM_ + d]);
            float4 bi = *reinterpret_cast<const float4*>(&g_bias[b * DIM_ + d]);
            float rx = fmaf(xv[u].x, sc.x, bi.x);
            float ry = fmaf(xv[u].y, sc.y, bi.y);
            float rz = fmaf(xv[u].z, sc.z, bi.z);
            float rw = fmaf(xv[u].w, sc.w, bi.w);
            uint2 o = {pack2h(rx, ry), pack2h(rz, rw)};
            reinterpret_cast<uint2*>(g_xn16)[i] = o;
        }
    } else {
        const int t = (blockIdx.x - LNB) * 256 + tid;
        float4 wv[4];
#pragma unroll
        for (int u = 0; u < 4; u++) {
            int i = t + u * CVT;
            if (i < NQKV4) {
                int elem = i * 4;
                int row = elem / QKVN_, col = elem % QKVN_;
                if (col < INNER_) {
                    wv[u] = *reinterpret_cast<const float4*>(
                        wq + (size_t)row * INNER_ + col);
                    wv[u].x *= QSCALE_; wv[u].y *= QSCALE_;
                    wv[u].z *= QSCALE_; wv[u].w *= QSCALE_;
                } else {
                    wv[u] = *reinterpret_cast<const float4*>(
                        wkv + (size_t)row * (2 * INNER_) + col - INNER_);
                }
            } else {
                wv[u] = reinterpret_cast<const float4*>(wo)[i - NQKV4];
            }
        }
#pragma unroll
        for (int u = 0; u < 4; u++) {
            int i = t + u * CVT;
            uint2 o = {pack2h(wv[u].x, wv[u].y), pack2h(wv[u].z, wv[u].w)};
            if (i < NQKV4)
                reinterpret_cast<uint2*>(g_wqkv16)[i] = o;
            else
                reinterpret_cast<uint2*>(g_wo16)[i - NQKV4] = o;
        }
    }
}

// ---------------------------------------------------------------------------
// qkv GEMM: BK=32, 3-stage cp.async, one sync per chunk (at HMMA floor).
// ---------------------------------------------------------------------------
__global__ void __launch_bounds__(256, 2)
gemm_qkv(const __half* __restrict__ A, const __half* __restrict__ B,
         __half* __restrict__ Qout, __half* __restrict__ KV, int K, int N) {
    constexpr uint32_t STAGE = 16384u;
    constexpr uint32_t BOFF  = 8192u;
    extern __shared__ char sm_[];
    const uint32_t sb = smem_u32(sm_);
    const int tid = threadIdx.x, lane = tid & 31, w = tid >> 5;
    const int wm = w >> 1, wn = w & 1, g = lane >> 2, t4 = lane & 3;
    const int row0 = blockIdx.y * 128, col0 = blockIdx.x * 128;
    const int KT = K >> 5;

    const int ar = tid >> 2, ac = tid & 3;
    const int br = tid >> 4, bc = tid & 15;

    auto issue = [&](int kt) {
        const uint32_t st = sb + (uint32_t)(kt % 3) * STAGE;
        const __half* pa = A + (size_t)(row0 + ar) * K + kt * 32 + ac * 8;
        cp16(st + swzA(ar, ac), pa);
        cp16(st + swzA(ar + 64, ac), pa + (size_t)64 * K);
        const __half* pb = B + (size_t)(kt * 32 + br) * N + col0 + bc * 8;
        cp16(st + BOFF + swzB(br, bc), pb);
        cp16(st + BOFF + swzB(br + 16, bc), pb + (size_t)16 * N);
        cp_commit();
    };

    float acc[2][8][4];
#pragma unroll
    for (int mi = 0; mi < 2; mi++)
#pragma unroll
        for (int ni = 0; ni < 8; ni++)
#pragma unroll
            for (int j = 0; j < 4; j++) acc[mi][ni][j] = 0.f;

    issue(0);
    issue(1);
    for (int kt = 0; kt < KT; kt++) {
        cp_wait1();
        __syncthreads();
        const uint32_t st = sb + (uint32_t)(kt % 3) * STAGE;
#pragma unroll
        for (int kk = 0; kk < 2; kk++) {
            uint32_t aH[2][4];
            const int arow = 32 * wm + (lane & 15);
            const int ach  = 2 * kk + (lane >> 4);
#pragma unroll
            for (int mi = 0; mi < 2; mi++)
                ldm_x4(aH[mi], st + swzA(arow + 16 * mi, ach));
            const int brow = 16 * kk + (lane & 7) + ((lane >> 3) & 1) * 8;
#pragma unroll
            for (int nn = 0; nn < 4; nn++) {
                const int bch = 8 * wn + 2 * nn + (lane >> 4);
                uint32_t bh[4];
                ldm_x4_t(bh, st + BOFF + swzB(brow, bch));
#pragma unroll
                for (int sub = 0; sub < 2; sub++) {
                    const int ni = 2 * nn + sub;
#pragma unroll
                    for (int mi = 0; mi < 2; mi++)
                        mma16816(acc[mi][ni], aH[mi], bh + 2 * sub);
                }
            }
        }
        if (kt + 2 < KT) issue(kt + 2);
        else cp_commit();
    }

#pragma unroll
    for (int mi = 0; mi < 2; mi++) {
        int rA = row0 + 32 * wm + 16 * mi + g;
#pragma unroll
        for (int ni = 0; ni < 8; ni++) {
            int col = col0 + 64 * wn + 8 * ni + 2 * t4;
            if (col0 < INNER_) {
                *reinterpret_cast<uint32_t*>(Qout + (size_t)rA * INNER_ + col) =
                    pack2h(acc[mi][ni][0], acc[mi][ni][1]);
                *reinterpret_cast<uint32_t*>(Qout + (size_t)(rA + 8) * INNER_ + col) =
                    pack2h(acc[mi][ni][2], acc[mi][ni][3]);
            } else {
                int ck = col - INNER_;
                *reinterpret_cast<uint32_t*>(KV + (size_t)rA * (2 * INNER_) + ck) =
                    pack2h(acc[mi][ni][0], acc[mi][ni][1]);
                *reinterpret_cast<uint32_t*>(KV + (size_t)(rA + 8) * (2 * INNER_) + ck) =
                    pack2h(acc[mi][ni][2], acc[mi][ni][3]);
            }
        }
    }
}

// ---------------------------------------------------------------------------
// Output GEMM: BK=64 chunks, 3-stage cp.async at 32KB/stage. fp32 out.
// ---------------------------------------------------------------------------
namespace { constexpr int OUT_SMEM = 3 * 32768; }

__global__ void __launch_bounds__(256, 2)
gemm_out(const __half* __restrict__ A, const __half* __restrict__ B,
         float* __restrict__ C, int K, int N) {
    extern __shared__ char sm_[];
    const uint32_t sb = smem_u32(sm_);
    const int tid = threadIdx.x, lane = tid & 31, w = tid >> 5;
    const int wm = w >> 1, wn = w & 1, g = lane >> 2, t4 = lane & 3;
    const int row0 = blockIdx.y * 128, col0 = blockIdx.x * 128;
    const int KT = K >> 6;

    const int ar = tid >> 3, ac = tid & 7;
    const int br = tid >> 4, bc = tid & 15;

    auto issue = [&](int kt) {
        const uint32_t st = sb + (uint32_t)(kt % 3) * 32768u;
        const __half* pa = A + (size_t)(row0 + ar) * K + kt * 64 + ac * 8;
#pragma unroll
        for (int it = 0; it < 4; it++)
            cp16(st + swzF(ar + 32 * it, ac), pa + (size_t)(32 * it) * K);
        const __half* pb = B + (size_t)(kt * 64 + br) * N + col0 + bc * 8;
#pragma unroll
        for (int it = 0; it < 4; it++)
            cp16(st + 16384u + swzB(br + 16 * it, bc), pb + (size_t)(16 * it) * N);
        cp_commit();
    };

    float acc[2][8][4];
#pragma unroll
    for (int mi = 0; mi < 2; mi++)
#pragma unroll
        for (int ni = 0; ni < 8; ni++)
#pragma unroll
            for (int j = 0; j < 4; j++) acc[mi][ni][j] = 0.f;

    issue(0);
    issue(1);
    for (int kt = 0; kt < KT; kt++) {
        cp_wait1();
        __syncthreads();
        const uint32_t st = sb + (uint32_t)(kt % 3) * 32768u;
#pragma unroll
        for (int kk = 0; kk < 4; kk++) {
            uint32_t aH[2][4];
            const int arow = 32 * wm + (lane & 15);
            const int ach  = 2 * kk + (lane >> 4);
#pragma unroll
            for (int mi = 0; mi < 2; mi++)
                ldm_x4(aH[mi], st + swzF(arow + 16 * mi, ach));
            const int brow = 16 * kk + (lane & 7) + ((lane >> 3) & 1) * 8;
#pragma unroll
            for (int nn = 0; nn < 4; nn++) {
                const int bch = 8 * wn + 2 * nn + (lane >> 4);
                uint32_t bh[4];
                ldm_x4_t(bh, st + 16384u + swzB(brow, bch));
#pragma unroll
                for (int sub = 0; sub < 2; sub++) {
                    const int ni = 2 * nn + sub;
#pragma unroll
                    for (int mi = 0; mi < 2; mi++)
                        mma16816(acc[mi][ni], aH[mi], bh + 2 * sub);
                }
            }
        }
        if (kt + 2 < KT) issue(kt + 2);
        else cp_commit();
    }

#pragma unroll
    for (int mi = 0; mi < 2; mi++) {
        int rA = row0 + 32 * wm + 16 * mi + g;
#pragma unroll
        for (int ni = 0; ni < 8; ni++) {
            int col = col0 + 64 * wn + 8 * ni + 2 * t4;
            float2 v0 = {acc[mi][ni][0], acc[mi][ni][1]};
            float2 v1 = {acc[mi][ni][2], acc[mi][ni][3]};
            *reinterpret_cast<float2*>(C + (size_t)rA * N + col) = v0;
            *reinterpret_cast<float2*>(C + (size_t)(rA + 8) * N + col) = v1;
        }
    }
}

// ---------------------------------------------------------------------------
// Flash attention (256 thr, 1 CTA/SM, 3-stage KV, split-KV across wn pair,
// shift-free softmax, base-2 fp16x2 exponentials). att stored single fp16.
// ---------------------------------------------------------------------------
namespace { constexpr int FLASH_SMEM = 114688 + 512; }

__global__ void __launch_bounds__(256)
flash_kernel(const __half* __restrict__ q16, const __half* __restrict__ kv,
             __half* __restrict__ att) {
    extern __shared__ char sm_[];
    const uint32_t sb = smem_u32(sm_);
    float* sL2 = (float*)(sm_ + 114688);

    const int tid = threadIdx.x, lane = tid & 31, w = tid >> 5;
    const int wm = w >> 1, wn = w & 1, g = lane >> 2, t4 = lane & 3;
    const int qt = blockIdx.x, h = blockIdx.y, b = blockIdx.z;
    const size_t qrow0 = (size_t)(b * N_ + qt * 128);

    {
        int r = tid >> 3, c = tid & 7;
        const __half* pq = q16 + (qrow0 + r) * INNER_ + h * 64 + c * 8;
#pragma unroll
        for (int it = 0; it < 4; it++)
            cp16(sb + swzF(r + 32 * it, c), pq + (size_t)(32 * it) * INNER_);
    }

    auto issueKV = [&](int kt) {
        const uint32_t st = sb + 16384u + (uint32_t)(kt % 3) * 32768u;
        int r = tid >> 3, c = tid & 7;
        size_t rowb = (size_t)(b * N_ + kt * 128);
        const __half* pk = kv + (rowb + r) * (2 * INNER_) + h * 64 + c * 8;
#pragma unroll
        for (int it = 0; it < 4; it++) {
            uint32_t o = swzF(r + 32 * it, c);
            size_t go = (size_t)(32 * it) * (2 * INNER_);
            cp16(st + o,           pk + go);
            cp16(st + 16384u + o,  pk + go + 512);
        }
        cp_commit();
    };

    issueKV(0);
    issueKV(1);

    float o[2][8][4];
    float ls[2][2];
#pragma unroll
    for (int mi = 0; mi < 2; mi++) {
        ls[mi][0] = 0.f; ls[mi][1] = 0.f;
#pragma unroll
        for (int ni = 0; ni < 8; ni++)
#pragma unroll
            for (int j = 0; j < 4; j++) o[mi][ni][j] = 0.f;
    }

    for (int kt = 0; kt < 16; kt++) {
        cp_wait1();
        __syncthreads();
        const uint32_t st = sb + 16384u + (uint32_t)(kt % 3) * 32768u;

        float s[2][8][4];
#pragma unroll
        for (int mi = 0; mi < 2; mi++)
#pragma unroll
            for (int ni = 0; ni < 8; ni++)
#pragma unroll
                for (int j = 0; j < 4; j++) s[mi][ni][j] = 0.f;

#pragma unroll
        for (int kk = 0; kk < 4; kk++) {
            uint32_t aH[2][4];
            const int arow = 32 * wm + (lane & 15);
            const int ach  = 2 * kk + (lane >> 4);
#pragma unroll
            for (int mi = 0; mi < 2; mi++)
                ldm_x4(aH[mi], sb + swzF(arow + 16 * mi, ach));
            const int krw = (lane & 7) + (lane >> 4) * 8;
            const int kch = 2 * kk + ((lane >> 3) & 1);
#pragma unroll
            for (int nn = 0; nn < 4; nn++) {
                uint32_t bh[4];
                ldm_x4(bh, st + swzF(64 * wn + 16 * nn + krw, kch));
#pragma unroll
                for (int sub = 0; sub < 2; sub++) {
                    const int ni = 2 * nn + sub;
#pragma unroll
                    for (int mi = 0; mi < 2; mi++)
                        mma16816(s[mi][ni], aH[mi], bh + 2 * sub);
                }
            }
        }

        uint32_t P[2][8][2];
#pragma unroll
        for (int mi = 0; mi < 2; mi++)
#pragma unroll
            for (int ni = 0; ni < 8; ni++) {
                P[mi][ni][0] = ex2_2h(s[mi][ni][0], s[mi][ni][1]);
                P[mi][ni][1] = ex2_2h(s[mi][ni][2], s[mi][ni][3]);
                float2 f0 = __half22float2(
                    *reinterpret_cast<__half2*>(&P[mi][ni][0]));
                float2 f1 = __half22float2(
                    *reinterpret_cast<__half2*>(&P[mi][ni][1]));
                ls[mi][0] += f0.x + f0.y;
                ls[mi][1] += f1.x + f1.y;
            }

#pragma unroll
        for (int kk2 = 0; kk2 < 4; kk2++) {
            uint32_t aP[2][4];
#pragma unroll
            for (int mi = 0; mi < 2; mi++) {
                aP[mi][0] = P[mi][2 * kk2][0];
                aP[mi][1] = P[mi][2 * kk2][1];
                aP[mi][2] = P[mi][2 * kk2 + 1][0];
                aP[mi][3] = P[mi][2 * kk2 + 1][1];
            }
            const int vrw = 64 * wn + 16 * kk2 + (lane & 7) + ((lane >> 3) & 1) * 8;
#pragma unroll
            for (int nn = 0; nn < 4; nn++) {
                const int vch = 2 * nn + (lane >> 4);
                uint32_t bh[4];
                ldm_x4_t(bh, st + 16384u + swzF(vrw, vch));
#pragma unroll
                for (int sub = 0; sub < 2; sub++) {
                    const int ni = 2 * nn + sub;
#pragma unroll
                    for (int mi = 0; mi < 2; mi++)
                        mma16816(o[mi][ni], aP[mi], bh + 2 * sub);
                }
            }
        }

        if (kt + 2 < 16) issueKV(kt + 2);
        else cp_commit();
    }

#pragma unroll
    for (int mi = 0; mi < 2; mi++)
#pragma unroll
        for (int j = 0; j < 2; j++) {
            ls[mi][j] += __shfl_xor_sync(0xffffffffu, ls[mi][j], 1);
            ls[mi][j] += __shfl_xor_sync(0xffffffffu, ls[mi][j], 2);
        }

    __syncthreads();
    float* sO = (float*)(sm_);
    if (wn == 1) {
#pragma unroll
        for (int mi = 0; mi < 2; mi++) {
            int rA = 32 * wm + 16 * mi + g;
            if (t4 == 0) {
                sL2[rA]     = ls[mi][0];
                sL2[rA + 8] = ls[mi][1];
            }
#pragma unroll
            for (int ni = 0; ni < 8; ni++) {
                int d = 8 * ni + 2 * t4;
                sO[rA * 64 + d]           = o[mi][ni][0];
                sO[rA * 64 + d + 1]       = o[mi][ni][1];
                sO[(rA + 8) * 64 + d]     = o[mi][ni][2];
                sO[(rA + 8) * 64 + d + 1] = o[mi][ni][3];
            }
        }
    }
    __syncthreads();
    if (wn == 0) {
#pragma unroll
        for (int mi = 0; mi < 2; mi++) {
            int rA = 32 * wm + 16 * mi + g;
            int rB = rA + 8;
            float iA = 1.f / (ls[mi][0] + sL2[rA]);
            float iB = 1.f / (ls[mi][1] + sL2[rB]);
#pragma unroll
            for (int ni = 0; ni < 8; ni++) {
                int d = 8 * ni + 2 * t4;
                float v0 = (o[mi][ni][0] + sO[rA * 64 + d])     * iA;
                float v1 = (o[mi][ni][1] + sO[rA * 64 + d + 1]) * iA;
                float v2 = (o[mi][ni][2] + sO[rB * 64 + d])     * iB;
                float v3 = (o[mi][ni][3] + sO[rB * 64 + d + 1]) * iB;
                *reinterpret_cast<uint32_t*>(att + (qrow0 + rA) * INNER_ + h * 64 + d) =
                    pack2h(v0, v1);
                *reinterpret_cast<uint32_t*>(att + (qrow0 + rB) * INNER_ + h * 64 + d) =
                    pack2h(v2, v3);
            }
        }
    }
}

// ---------------------------------------------------------------------------
extern "C" void kernel_launch(void* const* d_in, const int* /*in_sizes*/,
                              int /*n_in*/, void* d_out, int /*out_size*/) {
    const float* x   = (const float*)d_in[0];
    const float* g   = (const float*)d_in[1];
    const float* wq  = (const float*)d_in[2];
    const float* wkv = (const float*)d_in[3];
    const float* wo  = (const float*)d_in[4];
    float* out = (float*)d_out;

    __half *xn, *q, *kv, *att, *wqkv, *wo16;
    cudaGetSymbolAddress((void**)&xn,   g_xn16);
    cudaGetSymbolAddress((void**)&q,    g_q16);
    cudaGetSymbolAddress((void**)&kv,   g_kv16);
    cudaGetSymbolAddress((void**)&att,  g_att16);
    cudaGetSymbolAddress((void**)&wqkv, g_wqkv16);
    cudaGetSymbolAddress((void**)&wo16, g_wo16);

    cudaFuncSetAttribute((const void*)gemm_qkv,
                         cudaFuncAttributeMaxDynamicSharedMemorySize, 3 * 16384);
    cudaFuncSetAttribute((const void*)gemm_out,
                         cudaFuncAttributeMaxDynamicSharedMemorySize, OUT_SMEM);
    cudaFuncSetAttribute((const void*)flash_kernel,
                         cudaFuncAttributeMaxDynamicSharedMemorySize, FLASH_SMEM);

    // LayerNorm stats (sequence-axis)
    ln_partial_kernel<<<dim3(DIM_ / 256, NCHUNK_, B_), 256>>>(x);
    ln_stats_kernel<<<dim3(DIM_ / 256, 1, B_), 256>>>(g);

    // fused: LN normalize + weight conversion (MLP=4)
    prep_kernel<<<2048 + 512, 256>>>(x, wq, wkv, wo);

    // fused qkv projection: [4096 x 1536]
    gemm_qkv<<<dim3(QKVN_ / 128, (B_ * N_) / 128), 256, 3 * 16384>>>(
        xn, wqkv, q, kv, DIM_, QKVN_);

    // fused attention (split-KV flash, base-2 fp16x2 exp, att single fp16)
    flash_kernel<<<dim3(N_ / 128, HEADS_, B_), 256, FLASH_SMEM>>>(q, kv, att);

    // output projection: [4096 x 1024], BK=64 chunks
    gemm_out<<<dim3(DIM_ / 128, (B_ * N_) / 128), 256, OUT_SMEM>>>(
        att, wo16, out, INNER_, DIM_);
}